// round 7
// baseline (speedup 1.0000x reference)
#include <cuda_runtime.h>
#include <cuda_fp16.h>
#include <math.h>
#include <stdint.h>

// ---------------- problem constants ----------------
#define TTOK 8192
#define NEXP 8
#define TOPK 2
#define DIM  1024          // K of GEMM1, N of GEMM2
#define FFD  2048          // N of GEMM1, K of GEMM2

// ---------------- GEMM tiling (fp16 m16n8k16) ----------------
#define BM 128
#define BN 128
#define BKH 32                              // halves per row-chunk = K 32 = 64B rows
#define NS 4
#define A_STAGE_H (BM*BKH)                  // 4096 halves = 8KB
#define B_STAGE_H (BN*BKH)                  // 4096 halves = 8KB
#define STAGE_H (A_STAGE_H + B_STAGE_H)     // 8192 halves = 16KB
#define SMEM_BYTES (NS * STAGE_H * 2)       // 64KB

// half2-index permutation within each 16-half2 (32-half) chunk:
// orig k2 = c + 4q  ->  new pos = 4c + q  (fragment quad {c,c+4,c+8,c+12} contiguous)
__host__ __device__ __forceinline__ int hperm2(int k2) {
    return (k2 & ~15) | ((k2 & 3) << 2) | ((k2 >> 2) & 3);
}

// ---------------- device scratch ----------------
__device__ int    g_cnt[NEXP];
__device__ int    g_list[NEXP * TTOK];
__device__ float  g_wt[TTOK * TOPK];
__device__ __half g_xp[(size_t)TTOK * DIM];          // x, perm fp16        (16 MB)
__device__ __half g_h[(size_t)TTOK * TOPK * FFD];    // gelu out, perm fp16 (67 MB)
__device__ float  g_y[(size_t)TTOK * TOPK * DIM];    // per-slot outputs    (67 MB)
__device__ __half g_w1t[(size_t)NEXP * FFD * DIM];   // w1^T [E*FF][perm D] (32 MB)
__device__ __half g_w2t[(size_t)NEXP * DIM * FFD];   // w2^T [E][D][perm FF](32 MB)
__device__ float  g_zpart[TTOK / 8];
__device__ float  g_ppart[(TTOK / 8) * NEXP];

// ---------------- helpers ----------------
__device__ __forceinline__ uint32_t smem_u32(const void* p) {
    uint32_t a;
    asm("{ .reg .u64 t; cvta.to.shared.u64 t, %1; cvt.u32.u64 %0, t; }" : "=r"(a) : "l"(p));
    return a;
}
__device__ __forceinline__ void cp16(uint32_t saddr, const void* g) {
    asm volatile("cp.async.cg.shared.global [%0], [%1], 16;" :: "r"(saddr), "l"(g) : "memory");
}
#define CP_COMMIT() asm volatile("cp.async.commit_group;" ::: "memory")
#define CP_WAIT2()  asm volatile("cp.async.wait_group 2;" ::: "memory")

// m16n8k16 fp16 MMA, fp32 accum
__device__ __forceinline__ void mma_f16(float* c, uint32_t a0, uint32_t a1, uint32_t a2,
                                        uint32_t a3, uint32_t b0, uint32_t b1) {
    asm volatile(
        "mma.sync.aligned.m16n8k16.row.col.f32.f16.f16.f32 "
        "{%0,%1,%2,%3}, {%4,%5,%6,%7}, {%8,%9}, {%0,%1,%2,%3};"
        : "+f"(c[0]), "+f"(c[1]), "+f"(c[2]), "+f"(c[3])
        : "r"(a0), "r"(a1), "r"(a2), "r"(a3), "r"(b0), "r"(b1));
}

__device__ __forceinline__ float gelu_exact(float v) {
    return 0.5f * v * (1.0f + erff(v * 0.70710678118654752f));
}

// ---------------- init ----------------
__global__ void init_kernel() {
    if (threadIdx.x < NEXP) g_cnt[threadIdx.x] = 0;
}

// ---------------- pre-pass: permute x -> fp16 ----------------
__global__ void permute_x_kernel(const float* __restrict__ x) {
    size_t i = (size_t)blockIdx.x * blockDim.x + threadIdx.x;
    size_t n2 = (size_t)TTOK * DIM / 2;
    half2* xp2 = reinterpret_cast<half2*>(g_xp);
    const float2* x2 = reinterpret_cast<const float2*>(x);
    for (size_t j = i; j < n2; j += (size_t)gridDim.x * blockDim.x) {
        int t = (int)(j / (DIM / 2)), k2 = (int)(j % (DIM / 2));
        float2 v = x2[j];
        xp2[(size_t)t * (DIM / 2) + hperm2(k2)] = __floats2half2_rn(v.x, v.y);
    }
}
// w1 [D][E*FF] -> g_w1t [E*FF][perm(D)] fp16
__global__ void transpose_w1_kernel(const float* __restrict__ w1) {
    __shared__ float t[32][33];
    int bx = blockIdx.x * 32;   // N (E*FF)
    int by = blockIdx.y * 32;   // K (D)
    int x = threadIdx.x, y = threadIdx.y;
#pragma unroll
    for (int i = 0; i < 32; i += 8)
        t[y + i][x] = w1[(size_t)(by + y + i) * (NEXP * FFD) + bx + x];
    __syncthreads();
    int tid = y * 32 + x;
    int xh = tid & 15;          // k2 within 16
    int yy = tid >> 4;          // 0..15
    half2* o2 = reinterpret_cast<half2*>(g_w1t);
    int p2 = hperm2((by >> 1) + xh);
#pragma unroll
    for (int rr = 0; rr < 2; rr++) {
        int r = yy + rr * 16;
        o2[(size_t)(bx + r) * (DIM / 2) + p2] =
            __floats2half2_rn(t[2 * xh][r], t[2 * xh + 1][r]);
    }
}
// w2 per-expert [FF][D] -> g_w2t[e] [D][perm(FF)] fp16
__global__ void transpose_w2_kernel(const float* __restrict__ w2) {
    __shared__ float t[32][33];
    int e = blockIdx.z;
    const float* in = w2 + (size_t)e * FFD * DIM;
    half2* o2 = reinterpret_cast<half2*>(g_w2t + (size_t)e * DIM * FFD);
    int bx = blockIdx.x * 32;   // D
    int by = blockIdx.y * 32;   // FF (K of gemm2)
    int x = threadIdx.x, y = threadIdx.y;
#pragma unroll
    for (int i = 0; i < 32; i += 8)
        t[y + i][x] = in[(size_t)(by + y + i) * DIM + bx + x];
    __syncthreads();
    int tid = y * 32 + x;
    int xh = tid & 15;
    int yy = tid >> 4;
    int p2 = hperm2((by >> 1) + xh);
#pragma unroll
    for (int rr = 0; rr < 2; rr++) {
        int r = yy + rr * 16;
        o2[(size_t)(bx + r) * (FFD / 2) + p2] =
            __floats2half2_rn(t[2 * xh][r], t[2 * xh + 1][r]);
    }
}

// ---------------- routing ----------------
__global__ void routing_kernel(const float* __restrict__ x,
                               const float* __restrict__ rw) {
    __shared__ float s_rw[NEXP * DIM];
    __shared__ float s_z[8];
    __shared__ float s_p[8][NEXP];

    for (int i = threadIdx.x; i < NEXP * DIM; i += blockDim.x) s_rw[i] = rw[i];
    __syncthreads();

    int warp = threadIdx.x >> 5;
    int lane = threadIdx.x & 31;
    int t = blockIdx.x * 8 + warp;

    float acc[NEXP];
#pragma unroll
    for (int e = 0; e < NEXP; e++) acc[e] = 0.f;
    const float* xp = x + (size_t)t * DIM;
    for (int i = lane; i < DIM; i += 32) {
        float xv = xp[i];
#pragma unroll
        for (int e = 0; e < NEXP; e++) acc[e] = fmaf(xv, s_rw[e * DIM + i], acc[e]);
    }
#pragma unroll
    for (int e = 0; e < NEXP; e++) {
#pragma unroll
        for (int o = 16; o > 0; o >>= 1)
            acc[e] += __shfl_xor_sync(0xffffffffu, acc[e], o);
    }
    if (lane == 0) {
        float m = acc[0];
#pragma unroll
        for (int e = 1; e < NEXP; e++) m = fmaxf(m, acc[e]);
        float p[NEXP]; float s = 0.f;
#pragma unroll
        for (int e = 0; e < NEXP; e++) { p[e] = expf(acc[e] - m); s += p[e]; }
        float inv = 1.f / s;
#pragma unroll
        for (int e = 0; e < NEXP; e++) p[e] *= inv;
        int i1 = 0;
#pragma unroll
        for (int e = 1; e < NEXP; e++) if (p[e] > p[i1]) i1 = e;
        int i2 = (i1 == 0) ? 1 : 0;
#pragma unroll
        for (int e = 0; e < NEXP; e++) if (e != i1 && p[e] > p[i2]) i2 = e;
        float sw = p[i1] + p[i2];
        int pos1 = atomicAdd(&g_cnt[i1], 1);
        g_list[i1 * TTOK + pos1] = t * 2;
        int pos2 = atomicAdd(&g_cnt[i2], 1);
        g_list[i2 * TTOK + pos2] = t * 2 + 1;
        g_wt[t * 2 + 0] = p[i1] / sw;
        g_wt[t * 2 + 1] = p[i2] / sw;
        float lse = m + logf(s);
        s_z[warp] = lse * lse;
#pragma unroll
        for (int e = 0; e < NEXP; e++) s_p[warp][e] = p[e];
    }
    __syncthreads();
    if (threadIdx.x == 0) {
        float zz = 0.f;
#pragma unroll
        for (int w = 0; w < 8; w++) zz += s_z[w];
        g_zpart[blockIdx.x] = zz;
    }
    if (threadIdx.x < NEXP) {
        float pp = 0.f;
#pragma unroll
        for (int w = 0; w < 8; w++) pp += s_p[w][threadIdx.x];
        g_ppart[blockIdx.x * NEXP + threadIdx.x] = pp;
    }
}

// ---------------- fp16 mma.sync GEMM core: 128x128 tile, warp tile 64x32 ----
// 8 warps: wm=(wid&1)*64, wn=(wid>>1)*32.  K processed 32 per chunk.
struct GemmCore {
    float acc[4][4][4];

    __device__ __forceinline__ void run(const __half* agp, const __half* bgp,
                                        __half* smem, int NC, int tid) {
        int lane = tid & 31;
        int wid = tid >> 5;
        int wm = (wid & 1) * 64;
        int wn = (wid >> 1) * 32;

#pragma unroll
        for (int i = 0; i < 4; i++)
#pragma unroll
            for (int j = 0; j < 4; j++)
#pragma unroll
                for (int r = 0; r < 4; r++) acc[i][j][r] = 0.f;

        int row = tid >> 1;
        int seg = (tid & 1) * 16;   // halves

        auto issue = [&](int c) {
            __half* st = smem + (c & (NS - 1)) * STAGE_H;
            uint32_t sa = smem_u32(st + row * BKH + seg);
            const __half* ga = agp + c * BKH + seg;
            cp16(sa, ga); cp16(sa + 16, ga + 8);
            uint32_t sbb = smem_u32(st + A_STAGE_H + row * BKH + seg);
            const __half* gb = bgp + c * BKH;
            cp16(sbb, gb); cp16(sbb + 16, gb + 8);
            CP_COMMIT();
        };

#pragma unroll
        for (int c = 0; c < NS - 1; c++) issue(c);

        for (int c = 0; c < NC; c++) {
            CP_WAIT2();
            __syncthreads();
            if (c + NS - 1 < NC) issue(c + NS - 1);
            else CP_COMMIT();

            const __half* st = smem + (c & (NS - 1)) * STAGE_H;
            const __half* As = st;
            const __half* Bs = st + A_STAGE_H;

            uint4 bf[4];
#pragma unroll
            for (int nt = 0; nt < 4; nt++)
                bf[nt] = *reinterpret_cast<const uint4*>(
                    Bs + (wn + nt * 8 + (lane >> 2)) * BKH + (lane & 3) * 8);
#pragma unroll
            for (int mt = 0; mt < 4; mt++) {
                int r = wm + mt * 16 + (lane >> 2);
                uint4 lo = *reinterpret_cast<const uint4*>(
                    As + r * BKH + (lane & 3) * 8);
                uint4 hi = *reinterpret_cast<const uint4*>(
                    As + (r + 8) * BKH + (lane & 3) * 8);
#pragma unroll
                for (int nt = 0; nt < 4; nt++) {
                    mma_f16(acc[mt][nt], lo.x, hi.x, lo.y, hi.y, bf[nt].x, bf[nt].y);
                    mma_f16(acc[mt][nt], lo.z, hi.z, lo.w, hi.w, bf[nt].z, bf[nt].w);
                }
            }
        }
    }
};

// GEMM1: h[slot][perm] = fp16(gelu( x[tok] @ w1_e ))  M=cnt[e], N=FFD, K=DIM
__global__ void __launch_bounds__(256, 2) gemm1_mma() {
    int e = blockIdx.z;
    int cnt = g_cnt[e];
    int m0 = blockIdx.x * BM;
    if (m0 >= cnt) return;
    int n0 = blockIdx.y * BN;

    extern __shared__ __align__(16) __half smem[];
    int tid = threadIdx.x;

    int crow = tid >> 1;
    int aidx = (m0 + crow < cnt) ? (m0 + crow) : (cnt - 1);
    int atoks = g_list[e * TTOK + aidx];
    const __half* agp = g_xp + (size_t)(atoks >> 1) * DIM;
    const __half* bgp = g_w1t + ((size_t)e * FFD + n0 + crow) * DIM + (tid & 1) * 16;

    GemmCore core;
    core.run(agp, bgp, smem, DIM / BKH, tid);

    int lane = tid & 31;
    int wid = tid >> 5;
    int wm = (wid & 1) * 64;
    int wn = (wid >> 1) * 32;
#pragma unroll
    for (int mt = 0; mt < 4; mt++) {
        int rloc = wm + mt * 16 + (lane >> 2);
#pragma unroll
        for (int half_ = 0; half_ < 2; half_++) {
            int rm = m0 + rloc + half_ * 8;
            if (rm >= cnt) continue;
            int slot = g_list[e * TTOK + rm];
            half2* hp2 = reinterpret_cast<half2*>(g_h + (size_t)slot * FFD);
#pragma unroll
            for (int nt = 0; nt < 4; nt++) {
                int nn = n0 + wn + nt * 8 + (lane & 3) * 2;
                float v0 = core.acc[mt][nt][half_ * 2 + 0];
                float v1 = core.acc[mt][nt][half_ * 2 + 1];
                hp2[hperm2(nn >> 1)] =
                    __floats2half2_rn(gelu_exact(v0), gelu_exact(v1));
            }
        }
    }
}

// GEMM2: y[slot] = wt * ( h[slot] @ w2_e )  M=cnt[e], N=DIM, K=FFD
__global__ void __launch_bounds__(256, 2) gemm2_mma() {
    int e = blockIdx.z;
    int cnt = g_cnt[e];
    int m0 = blockIdx.x * BM;
    if (m0 >= cnt) return;
    int n0 = blockIdx.y * BN;

    extern __shared__ __align__(16) __half smem[];
    int tid = threadIdx.x;

    int crow = tid >> 1;
    int aidx = (m0 + crow < cnt) ? (m0 + crow) : (cnt - 1);
    int aslot = g_list[e * TTOK + aidx];
    const __half* agp = g_h + (size_t)aslot * FFD;
    const __half* bgp = g_w2t + ((size_t)e * DIM + n0 + crow) * FFD + (tid & 1) * 16;

    GemmCore core;
    core.run(agp, bgp, smem, FFD / BKH, tid);

    int lane = tid & 31;
    int wid = tid >> 5;
    int wm = (wid & 1) * 64;
    int wn = (wid >> 1) * 32;
#pragma unroll
    for (int mt = 0; mt < 4; mt++) {
        int rloc = wm + mt * 16 + (lane >> 2);
#pragma unroll
        for (int half_ = 0; half_ < 2; half_++) {
            int rm = m0 + rloc + half_ * 8;
            if (rm >= cnt) continue;
            int slot = g_list[e * TTOK + rm];
            float wv = g_wt[slot];
            float* yp = g_y + (size_t)slot * DIM + n0;
#pragma unroll
            for (int nt = 0; nt < 4; nt++) {
                float2 v;
                v.x = wv * core.acc[mt][nt][half_ * 2 + 0];
                v.y = wv * core.acc[mt][nt][half_ * 2 + 1];
                *reinterpret_cast<float2*>(yp + wn + nt * 8 + (lane & 3) * 2) = v;
            }
        }
    }
}

// ---------------- combine: out[t] = y[2t] + y[2t+1] ----------------
__global__ void combine_kernel(float* __restrict__ out) {
    size_t i = (size_t)blockIdx.x * blockDim.x + threadIdx.x;
    size_t n4 = (size_t)TTOK * DIM / 4;
    const float4* y4 = reinterpret_cast<const float4*>(g_y);
    for (size_t j = i; j < n4; j += (size_t)gridDim.x * blockDim.x) {
        size_t t = j / (DIM / 4);
        size_t d = j % (DIM / 4);
        float4 a = y4[(2 * t) * (DIM / 4) + d];
        float4 b = y4[(2 * t + 1) * (DIM / 4) + d];
        float4 o;
        o.x = a.x + b.x; o.y = a.y + b.y; o.z = a.z + b.z; o.w = a.w + b.w;
        reinterpret_cast<float4*>(out)[j] = o;
    }
}

// ---------------- finalize losses ----------------
__global__ void finalize_kernel(float* __restrict__ out) {
    __shared__ float s_p[NEXP];
    __shared__ float s_z;
    int tid = threadIdx.x;
    if (tid < NEXP) {
        float s = 0.f;
        for (int b = 0; b < TTOK / 8; b++) s += g_ppart[b * NEXP + tid];
        s_p[tid] = s;
    }
    if (tid == 8) {
        float s = 0.f;
        for (int b = 0; b < TTOK / 8; b++) s += g_zpart[b];
        s_z = s;
    }
    __syncthreads();
    if (tid == 0) {
        float z = s_z / (float)TTOK;
        float lb = 0.f;
        for (int e = 0; e < NEXP; e++)
            lb += ((float)g_cnt[e] / (float)(TTOK * TOPK)) * (s_p[e] / (float)TTOK);
        lb *= (float)NEXP;
        out[(size_t)TTOK * DIM + 0] = z;
        out[(size_t)TTOK * DIM + 1] = lb;
    }
}

// ---------------- launch ----------------
extern "C" void kernel_launch(void* const* d_in, const int* in_sizes, int n_in,
                              void* d_out, int out_size) {
    const float* x  = (const float*)d_in[0];
    const float* rw = (const float*)d_in[1];
    const float* w1 = (const float*)d_in[2];
    const float* w2 = (const float*)d_in[3];
    float* out = (float*)d_out;

    cudaFuncSetAttribute(gemm1_mma, cudaFuncAttributeMaxDynamicSharedMemorySize, SMEM_BYTES);
    cudaFuncSetAttribute(gemm2_mma, cudaFuncAttributeMaxDynamicSharedMemorySize, SMEM_BYTES);

    init_kernel<<<1, 32>>>();
    permute_x_kernel<<<2048, 256>>>(x);
    transpose_w1_kernel<<<dim3(NEXP * FFD / 32, DIM / 32), dim3(32, 8)>>>(w1);
    transpose_w2_kernel<<<dim3(DIM / 32, FFD / 32, NEXP), dim3(32, 8)>>>(w2);
    routing_kernel<<<TTOK / 8, 256>>>(x, rw);

    gemm1_mma<<<dim3(TTOK / BM, FFD / BN, NEXP), 256, SMEM_BYTES>>>();
    gemm2_mma<<<dim3(TTOK / BM, DIM / BN, NEXP), 256, SMEM_BYTES>>>();

    combine_kernel<<<2048, 256>>>(out);
    finalize_kernel<<<1, 32>>>(out);
}

// round 8
// speedup vs baseline: 1.0153x; 1.0153x over previous
#include <cuda_runtime.h>
#include <cuda_fp16.h>
#include <math.h>
#include <stdint.h>

// ---------------- problem constants ----------------
#define TTOK 8192
#define NEXP 8
#define TOPK 2
#define DIM  1024          // K of GEMM1, N of GEMM2
#define FFD  2048          // N of GEMM1, K of GEMM2

// ---------------- GEMM tiling (fp16 m16n8k16) ----------------
#define BM 128
#define BN 128
#define BKH 32                              // halves per row-chunk = K 32 = 64B rows
#define NS 4
#define A_STAGE_H (BM*BKH)                  // 4096 halves = 8KB
#define B_STAGE_H (BN*BKH)                  // 4096 halves = 8KB
#define STAGE_H (A_STAGE_H + B_STAGE_H)     // 8192 halves = 16KB
#define SMEM_BYTES (NS * STAGE_H * 2)       // 64KB

// half2-index permutation within each 16-half2 (32-half) chunk:
// orig k2 = c + 4q  ->  new pos = 4c + q  (fragment quad {c,c+4,c+8,c+12} contiguous)
__host__ __device__ __forceinline__ int hperm2(int k2) {
    return (k2 & ~15) | ((k2 & 3) << 2) | ((k2 >> 2) & 3);
}

// ---------------- device scratch ----------------
__device__ int    g_cnt[NEXP];
__device__ int    g_list[NEXP * TTOK];
__device__ float  g_wt[TTOK * TOPK];
__device__ __half g_xp[(size_t)TTOK * DIM];          // x, perm fp16        (16 MB)
__device__ __half g_h[(size_t)TTOK * TOPK * FFD];    // gelu out, perm fp16 (67 MB)
__device__ __half g_w1t[(size_t)NEXP * FFD * DIM];   // w1^T [E*FF][perm D] (32 MB)
__device__ __half g_w2t[(size_t)NEXP * DIM * FFD];   // w2^T [E][D][perm FF](32 MB)
__device__ float  g_zpart[TTOK / 8];
__device__ float  g_ppart[(TTOK / 8) * NEXP];

// ---------------- helpers ----------------
__device__ __forceinline__ uint32_t smem_u32(const void* p) {
    uint32_t a;
    asm("{ .reg .u64 t; cvta.to.shared.u64 t, %1; cvt.u32.u64 %0, t; }" : "=r"(a) : "l"(p));
    return a;
}
__device__ __forceinline__ void cp16(uint32_t saddr, const void* g) {
    asm volatile("cp.async.cg.shared.global [%0], [%1], 16;" :: "r"(saddr), "l"(g) : "memory");
}
#define CP_COMMIT() asm volatile("cp.async.commit_group;" ::: "memory")
#define CP_WAIT2()  asm volatile("cp.async.wait_group 2;" ::: "memory")

// m16n8k16 fp16 MMA, fp32 accum
__device__ __forceinline__ void mma_f16(float* c, uint32_t a0, uint32_t a1, uint32_t a2,
                                        uint32_t a3, uint32_t b0, uint32_t b1) {
    asm volatile(
        "mma.sync.aligned.m16n8k16.row.col.f32.f16.f16.f32 "
        "{%0,%1,%2,%3}, {%4,%5,%6,%7}, {%8,%9}, {%0,%1,%2,%3};"
        : "+f"(c[0]), "+f"(c[1]), "+f"(c[2]), "+f"(c[3])
        : "r"(a0), "r"(a1), "r"(a2), "r"(a3), "r"(b0), "r"(b1));
}

__device__ __forceinline__ float gelu_exact(float v) {
    return 0.5f * v * (1.0f + erff(v * 0.70710678118654752f));
}

// ---------------- init: zero out tensor + counters ----------------
__global__ void init_kernel(float* __restrict__ out) {
    long i = (long)blockIdx.x * blockDim.x + threadIdx.x;
    long n4 = (long)TTOK * DIM / 4;
    float4 z = make_float4(0.f, 0.f, 0.f, 0.f);
    for (long j = i; j < n4; j += (long)gridDim.x * blockDim.x)
        reinterpret_cast<float4*>(out)[j] = z;
    if (i < NEXP) g_cnt[(int)i] = 0;
}

// ---------------- transposes with coalesced 16B permuted stores -------------
// w1 [D][E*FF] -> g_w1t [E*FF][perm(D)] fp16
__global__ void transpose_w1_kernel(const float* __restrict__ w1) {
    __shared__ float t[32][33];
    int bx = blockIdx.x * 32;   // N (E*FF)
    int by = blockIdx.y * 32;   // K (D), 32 floats = one 16-half2 perm chunk
    int x = threadIdx.x, y = threadIdx.y;
#pragma unroll
    for (int i = 0; i < 32; i += 8)
        t[y + i][x] = w1[(size_t)(by + y + i) * (NEXP * FFD) + bx + x];
    __syncthreads();
    int tid = y * 32 + x;
    if (tid < 128) {
        int r = tid >> 2;        // output row 0..31
        int c = tid & 3;         // perm c-group; covers positions 4c..4c+3
        half2 h[4];
#pragma unroll
        for (int q = 0; q < 4; q++) {
            int j = c + 4 * q;   // orig k2 within chunk
            h[q] = __floats2half2_rn(t[2 * j][r], t[2 * j + 1][r]);
        }
        half2* o2 = reinterpret_cast<half2*>(g_w1t) +
                    (size_t)(bx + r) * (DIM / 2) + (by >> 1) + 4 * c;
        *reinterpret_cast<uint4*>(o2) = *reinterpret_cast<uint4*>(h);
    }
}
// w2 per-expert [FF][D] -> g_w2t[e] [D][perm(FF)] fp16
__global__ void transpose_w2_kernel(const float* __restrict__ w2) {
    __shared__ float t[32][33];
    int e = blockIdx.z;
    const float* in = w2 + (size_t)e * FFD * DIM;
    int bx = blockIdx.x * 32;   // D
    int by = blockIdx.y * 32;   // FF (K of gemm2)
    int x = threadIdx.x, y = threadIdx.y;
#pragma unroll
    for (int i = 0; i < 32; i += 8)
        t[y + i][x] = in[(size_t)(by + y + i) * DIM + bx + x];
    __syncthreads();
    int tid = y * 32 + x;
    if (tid < 128) {
        int r = tid >> 2;
        int c = tid & 3;
        half2 h[4];
#pragma unroll
        for (int q = 0; q < 4; q++) {
            int j = c + 4 * q;
            h[q] = __floats2half2_rn(t[2 * j][r], t[2 * j + 1][r]);
        }
        half2* o2 = reinterpret_cast<half2*>(g_w2t + (size_t)e * DIM * FFD) +
                    (size_t)(bx + r) * (FFD / 2) + (by >> 1) + 4 * c;
        *reinterpret_cast<uint4*>(o2) = *reinterpret_cast<uint4*>(h);
    }
}

// ---------------- routing + fused x permute/convert ----------------
__global__ void routing_kernel(const float* __restrict__ x,
                               const float* __restrict__ rw) {
    __shared__ float s_rw[NEXP * DIM];
    __shared__ float s_z[8];
    __shared__ float s_p[8][NEXP];

    for (int i = threadIdx.x; i < NEXP * DIM; i += blockDim.x) s_rw[i] = rw[i];
    __syncthreads();

    int warp = threadIdx.x >> 5;
    int lane = threadIdx.x & 31;
    int t = blockIdx.x * 8 + warp;

    float acc[NEXP];
#pragma unroll
    for (int e = 0; e < NEXP; e++) acc[e] = 0.f;
    const float2* xp2 = reinterpret_cast<const float2*>(x) + (size_t)t * (DIM / 2);
    half2* gx2 = reinterpret_cast<half2*>(g_xp) + (size_t)t * (DIM / 2);
#pragma unroll
    for (int it = 0; it < DIM / 2 / 32; it++) {
        int k2 = it * 32 + lane;
        float2 v = xp2[k2];
        gx2[hperm2(k2)] = __floats2half2_rn(v.x, v.y);   // fused permute+fp16
#pragma unroll
        for (int e = 0; e < NEXP; e++) {
            acc[e] = fmaf(v.x, s_rw[e * DIM + 2 * k2], acc[e]);
            acc[e] = fmaf(v.y, s_rw[e * DIM + 2 * k2 + 1], acc[e]);
        }
    }
#pragma unroll
    for (int e = 0; e < NEXP; e++) {
#pragma unroll
        for (int o = 16; o > 0; o >>= 1)
            acc[e] += __shfl_xor_sync(0xffffffffu, acc[e], o);
    }
    if (lane == 0) {
        float m = acc[0];
#pragma unroll
        for (int e = 1; e < NEXP; e++) m = fmaxf(m, acc[e]);
        float p[NEXP]; float s = 0.f;
#pragma unroll
        for (int e = 0; e < NEXP; e++) { p[e] = expf(acc[e] - m); s += p[e]; }
        float inv = 1.f / s;
#pragma unroll
        for (int e = 0; e < NEXP; e++) p[e] *= inv;
        int i1 = 0;
#pragma unroll
        for (int e = 1; e < NEXP; e++) if (p[e] > p[i1]) i1 = e;
        int i2 = (i1 == 0) ? 1 : 0;
#pragma unroll
        for (int e = 0; e < NEXP; e++) if (e != i1 && p[e] > p[i2]) i2 = e;
        float sw = p[i1] + p[i2];
        int pos1 = atomicAdd(&g_cnt[i1], 1);
        g_list[i1 * TTOK + pos1] = t * 2;
        int pos2 = atomicAdd(&g_cnt[i2], 1);
        g_list[i2 * TTOK + pos2] = t * 2 + 1;
        g_wt[t * 2 + 0] = p[i1] / sw;
        g_wt[t * 2 + 1] = p[i2] / sw;
        float lse = m + logf(s);
        s_z[warp] = lse * lse;
#pragma unroll
        for (int e = 0; e < NEXP; e++) s_p[warp][e] = p[e];
    }
    __syncthreads();
    if (threadIdx.x == 0) {
        float zz = 0.f;
#pragma unroll
        for (int w = 0; w < 8; w++) zz += s_z[w];
        g_zpart[blockIdx.x] = zz;
    }
    if (threadIdx.x < NEXP) {
        float pp = 0.f;
#pragma unroll
        for (int w = 0; w < 8; w++) pp += s_p[w][threadIdx.x];
        g_ppart[blockIdx.x * NEXP + threadIdx.x] = pp;
    }
}

// ---------------- fp16 mma.sync GEMM core: 128x128 tile, warp tile 64x32 ----
struct GemmCore {
    float acc[4][4][4];

    __device__ __forceinline__ void run(const __half* agp, const __half* bgp,
                                        __half* smem, int NC, int tid) {
        int lane = tid & 31;
        int wid = tid >> 5;
        int wm = (wid & 1) * 64;
        int wn = (wid >> 1) * 32;

#pragma unroll
        for (int i = 0; i < 4; i++)
#pragma unroll
            for (int j = 0; j < 4; j++)
#pragma unroll
                for (int r = 0; r < 4; r++) acc[i][j][r] = 0.f;

        int row = tid >> 1;
        int seg = (tid & 1) * 16;   // halves

        auto issue = [&](int c) {
            __half* st = smem + (c & (NS - 1)) * STAGE_H;
            uint32_t sa = smem_u32(st + row * BKH + seg);
            const __half* ga = agp + c * BKH + seg;
            cp16(sa, ga); cp16(sa + 16, ga + 8);
            uint32_t sbb = smem_u32(st + A_STAGE_H + row * BKH + seg);
            const __half* gb = bgp + c * BKH;
            cp16(sbb, gb); cp16(sbb + 16, gb + 8);
            CP_COMMIT();
        };

#pragma unroll
        for (int c = 0; c < NS - 1; c++) issue(c);

        for (int c = 0; c < NC; c++) {
            CP_WAIT2();
            __syncthreads();
            if (c + NS - 1 < NC) issue(c + NS - 1);
            else CP_COMMIT();

            const __half* st = smem + (c & (NS - 1)) * STAGE_H;
            const __half* As = st;
            const __half* Bs = st + A_STAGE_H;

            uint4 bf[4];
#pragma unroll
            for (int nt = 0; nt < 4; nt++)
                bf[nt] = *reinterpret_cast<const uint4*>(
                    Bs + (wn + nt * 8 + (lane >> 2)) * BKH + (lane & 3) * 8);
#pragma unroll
            for (int mt = 0; mt < 4; mt++) {
                int r = wm + mt * 16 + (lane >> 2);
                uint4 lo = *reinterpret_cast<const uint4*>(
                    As + r * BKH + (lane & 3) * 8);
                uint4 hi = *reinterpret_cast<const uint4*>(
                    As + (r + 8) * BKH + (lane & 3) * 8);
#pragma unroll
                for (int nt = 0; nt < 4; nt++) {
                    mma_f16(acc[mt][nt], lo.x, hi.x, lo.y, hi.y, bf[nt].x, bf[nt].y);
                    mma_f16(acc[mt][nt], lo.z, hi.z, lo.w, hi.w, bf[nt].z, bf[nt].w);
                }
            }
        }
    }
};

// GEMM1: h[slot][perm] = fp16(gelu( x[tok] @ w1_e ))  M=cnt[e], N=FFD, K=DIM
__global__ void __launch_bounds__(256) gemm1_mma() {
    int e = blockIdx.z;
    int cnt = g_cnt[e];
    int m0 = blockIdx.x * BM;
    if (m0 >= cnt) return;
    int n0 = blockIdx.y * BN;

    extern __shared__ __align__(16) __half smem[];
    int tid = threadIdx.x;

    int crow = tid >> 1;
    int aidx = (m0 + crow < cnt) ? (m0 + crow) : (cnt - 1);
    int atoks = g_list[e * TTOK + aidx];
    const __half* agp = g_xp + (size_t)(atoks >> 1) * DIM;
    const __half* bgp = g_w1t + ((size_t)e * FFD + n0 + crow) * DIM + (tid & 1) * 16;

    GemmCore core;
    core.run(agp, bgp, smem, DIM / BKH, tid);

    int lane = tid & 31;
    int wid = tid >> 5;
    int wm = (wid & 1) * 64;
    int wn = (wid >> 1) * 32;
#pragma unroll
    for (int mt = 0; mt < 4; mt++) {
        int rloc = wm + mt * 16 + (lane >> 2);
#pragma unroll
        for (int half_ = 0; half_ < 2; half_++) {
            int rm = m0 + rloc + half_ * 8;
            if (rm >= cnt) continue;
            int slot = g_list[e * TTOK + rm];
            half2* hp2 = reinterpret_cast<half2*>(g_h + (size_t)slot * FFD);
#pragma unroll
            for (int nt = 0; nt < 4; nt++) {
                int nn = n0 + wn + nt * 8 + (lane & 3) * 2;
                float v0 = core.acc[mt][nt][half_ * 2 + 0];
                float v1 = core.acc[mt][nt][half_ * 2 + 1];
                hp2[hperm2(nn >> 1)] =
                    __floats2half2_rn(gelu_exact(v0), gelu_exact(v1));
            }
        }
    }
}

// GEMM2: out[tok] += wt * ( h[slot] @ w2_e )  -- direct atomicAdd epilogue.
// Exactly 2 contributions per out element; fp add is commutative so the result
// is bitwise-deterministic over the zeroed output.
__global__ void __launch_bounds__(256) gemm2_mma(float* __restrict__ out) {
    int e = blockIdx.z;
    int cnt = g_cnt[e];
    int m0 = blockIdx.x * BM;
    if (m0 >= cnt) return;
    int n0 = blockIdx.y * BN;

    extern __shared__ __align__(16) __half smem[];
    int tid = threadIdx.x;

    int crow = tid >> 1;
    int aidx = (m0 + crow < cnt) ? (m0 + crow) : (cnt - 1);
    int aslot = g_list[e * TTOK + aidx];
    const __half* agp = g_h + (size_t)aslot * FFD;
    const __half* bgp = g_w2t + ((size_t)e * DIM + n0 + crow) * FFD + (tid & 1) * 16;

    GemmCore core;
    core.run(agp, bgp, smem, FFD / BKH, tid);

    int lane = tid & 31;
    int wid = tid >> 5;
    int wm = (wid & 1) * 64;
    int wn = (wid >> 1) * 32;
#pragma unroll
    for (int mt = 0; mt < 4; mt++) {
        int rloc = wm + mt * 16 + (lane >> 2);
#pragma unroll
        for (int half_ = 0; half_ < 2; half_++) {
            int rm = m0 + rloc + half_ * 8;
            if (rm >= cnt) continue;
            int slot = g_list[e * TTOK + rm];
            float wv = g_wt[slot];
            float* op = out + (size_t)(slot >> 1) * DIM + n0;
#pragma unroll
            for (int nt = 0; nt < 4; nt++) {
                int nn = wn + nt * 8 + (lane & 3) * 2;
                atomicAdd(&op[nn + 0], wv * core.acc[mt][nt][half_ * 2 + 0]);
                atomicAdd(&op[nn + 1], wv * core.acc[mt][nt][half_ * 2 + 1]);
            }
        }
    }
}

// ---------------- finalize losses ----------------
__global__ void finalize_kernel(float* __restrict__ out) {
    __shared__ float s_p[NEXP];
    __shared__ float s_z;
    int tid = threadIdx.x;
    if (tid < NEXP) {
        float s = 0.f;
        for (int b = 0; b < TTOK / 8; b++) s += g_ppart[b * NEXP + tid];
        s_p[tid] = s;
    }
    if (tid == 8) {
        float s = 0.f;
        for (int b = 0; b < TTOK / 8; b++) s += g_zpart[b];
        s_z = s;
    }
    __syncthreads();
    if (tid == 0) {
        float z = s_z / (float)TTOK;
        float lb = 0.f;
        for (int e = 0; e < NEXP; e++)
            lb += ((float)g_cnt[e] / (float)(TTOK * TOPK)) * (s_p[e] / (float)TTOK);
        lb *= (float)NEXP;
        out[(size_t)TTOK * DIM + 0] = z;
        out[(size_t)TTOK * DIM + 1] = lb;
    }
}

// ---------------- launch ----------------
extern "C" void kernel_launch(void* const* d_in, const int* in_sizes, int n_in,
                              void* d_out, int out_size) {
    const float* x  = (const float*)d_in[0];
    const float* rw = (const float*)d_in[1];
    const float* w1 = (const float*)d_in[2];
    const float* w2 = (const float*)d_in[3];
    float* out = (float*)d_out;

    cudaFuncSetAttribute(gemm1_mma, cudaFuncAttributeMaxDynamicSharedMemorySize, SMEM_BYTES);
    cudaFuncSetAttribute(gemm2_mma, cudaFuncAttributeMaxDynamicSharedMemorySize, SMEM_BYTES);

    init_kernel<<<2048, 256>>>(out);
    transpose_w1_kernel<<<dim3(NEXP * FFD / 32, DIM / 32), dim3(32, 8)>>>(w1);
    transpose_w2_kernel<<<dim3(DIM / 32, FFD / 32, NEXP), dim3(32, 8)>>>(w2);
    routing_kernel<<<TTOK / 8, 256>>>(x, rw);

    gemm1_mma<<<dim3(TTOK / BM, FFD / BN, NEXP), 256, SMEM_BYTES>>>();
    gemm2_mma<<<dim3(TTOK / BM, DIM / BN, NEXP), 256, SMEM_BYTES>>>(out);

    finalize_kernel<<<1, 32>>>(out);
}